// round 1
// baseline (speedup 1.0000x reference)
#include <cuda_runtime.h>
#include <cuda_bf16.h>

#define LMAX 13
#define N_TYPES 20
#define NRES_MAX 2048
#define BMAX 16
#define DV 64
#define TPB 192   // = DV * 3

// per-amino-acid residue lengths (fixed problem constant, matches reference RES_LEN_NP)
__constant__ int c_res_len[N_TYPES] = {3,4,5,5,6,6,6,7,7,7,7,7,8,8,8,9,10,10,11,13};

// exclusive prefix sums of residue lengths (scratch; no allocation allowed)
__device__ int g_starts[NRES_MAX];

// ---------------------------------------------------------------------------
// Kernel 1: exclusive scan of residue lengths -> g_starts. One block.
// n_res <= 2048, 1024 threads, each handles 2 elements.
// ---------------------------------------------------------------------------
__global__ void scan_starts_kernel(const int* __restrict__ seq, int n_res) {
    __shared__ int s[1024];
    int tid = threadIdx.x;
    int i0 = 2 * tid, i1 = 2 * tid + 1;
    int l0 = (i0 < n_res) ? c_res_len[seq[i0]] : 0;
    int l1 = (i1 < n_res) ? c_res_len[seq[i1]] : 0;
    int pair = l0 + l1;
    s[tid] = pair;
    __syncthreads();
    // Hillis-Steele inclusive scan over pair sums
    #pragma unroll
    for (int off = 1; off < 1024; off <<= 1) {
        int v = (tid >= off) ? s[tid - off] : 0;
        __syncthreads();
        s[tid] += v;
        __syncthreads();
    }
    int excl = s[tid] - pair;
    if (i0 < n_res) g_starts[i0] = excl;
    if (i1 < n_res) g_starts[i1] = excl + l0;
}

// ---------------------------------------------------------------------------
// Kernel 2: main fused gather + dual-einsum + scatter.
// One block per residue, covering ALL batches.
// Thread mapping: tid = v*3 + d  (v in [0,64), d in [0,3)) so each (b, atom)
// output row of 192 floats is written fully coalesced by the block.
// diff is register-blocked 4 batches at a time: each W element read from
// shared feeds 4 FMAs.
// ---------------------------------------------------------------------------
__global__ __launch_bounds__(TPB) void posmix_kernel(
    const float* __restrict__ pos_atm,   // (B, atoms, 3)
    const float* __restrict__ pos_amn,   // (B, n_res, 3)
    const float* __restrict__ W_amn,     // (20, 64, 13)
    const float* __restrict__ W_atm,     // (20, 13, 64, 13)
    const int*   __restrict__ seq,       // (n_res,)
    float* __restrict__ out_atm,         // (B, atoms, 64, 3)
    float* __restrict__ out_amn,         // (B, n_res, 64, 3)
    int B, int n_res, int atoms)
{
    __shared__ float sW[LMAX * DV * LMAX];     // staged W_atm[t][0:L]  (<=43264 B)
    __shared__ float sdiff[BMAX * LMAX * 3];   // diff, zero-padded to LMAX (2496 B)

    const int i   = blockIdx.x;
    const int tid = threadIdx.x;
    const int t   = seq[i];
    const int L   = c_res_len[t];
    const int start = g_starts[i];

    // --- stage W_atm[t][0:L][*][*] (contiguous) ---
    const float* gW = W_atm + (size_t)t * (LMAX * DV * LMAX);
    const int nW = L * DV * LMAX;
    for (int idx = tid; idx < nW; idx += TPB) sW[idx] = gW[idx];

    // --- stage diffs for all batches, zero-padded in l ---
    const int nd = B * LMAX * 3;
    for (int idx = tid; idx < nd; idx += TPB) {
        int b = idx / (LMAX * 3);
        int r = idx - b * (LMAX * 3);
        int l = r / 3;
        int d = r - l * 3;
        float val = 0.0f;
        if (l < L) {
            val = pos_atm[((size_t)b * atoms + start + l) * 3 + d]
                - pos_amn[((size_t)b * n_res + i) * 3 + d];
        }
        sdiff[idx] = val;
    }
    __syncthreads();

    const int v = tid / 3;
    const int d = tid - v * 3;
    const float* gWa = W_amn + ((size_t)t * DV + v) * LMAX;

    for (int bb0 = 0; bb0 < B; bb0 += 4) {
        // pull 4 batches of this thread's diff column into registers
        float dv0[LMAX], dv1[LMAX], dv2[LMAX], dv3[LMAX];
        #pragma unroll
        for (int l = 0; l < LMAX; l++) {
            dv0[l] = sdiff[((bb0 + 0) * LMAX + l) * 3 + d];
            dv1[l] = sdiff[((bb0 + 1) * LMAX + l) * 3 + d];
            dv2[l] = sdiff[((bb0 + 2) * LMAX + l) * 3 + d];
            dv3[l] = sdiff[((bb0 + 3) * LMAX + l) * 3 + d];
        }

        // ---- x_v_amn: (64 x L) @ (L x 3) ----
        {
            float a0 = 0.f, a1 = 0.f, a2 = 0.f, a3 = 0.f;
            #pragma unroll
            for (int l = 0; l < LMAX; l++) {
                float w = gWa[l];          // L1/L2-cached, shared by 3 d-threads
                a0 += w * dv0[l];
                a1 += w * dv1[l];
                a2 += w * dv2[l];
                a3 += w * dv3[l];
            }
            const size_t o0 = (((size_t)(bb0 + 0) * n_res + i) * DV + v) * 3 + d;
            const size_t o1 = (((size_t)(bb0 + 1) * n_res + i) * DV + v) * 3 + d;
            const size_t o2 = (((size_t)(bb0 + 2) * n_res + i) * DV + v) * 3 + d;
            const size_t o3 = (((size_t)(bb0 + 3) * n_res + i) * DV + v) * 3 + d;
            out_amn[o0] = a0; out_amn[o1] = a1; out_amn[o2] = a2; out_amn[o3] = a3;
        }

        // ---- x_v_atm: for each output atom m: (64 x L) @ (L x 3) ----
        for (int m = 0; m < L; m++) {
            const float* wr = &sW[(m * DV + v) * LMAX];
            float a0 = 0.f, a1 = 0.f, a2 = 0.f, a3 = 0.f;
            #pragma unroll
            for (int l = 0; l < LMAX; l++) {
                float w = wr[l];
                a0 += w * dv0[l];
                a1 += w * dv1[l];
                a2 += w * dv2[l];
                a3 += w * dv3[l];
            }
            const size_t row = (size_t)(start + m) * (DV * 3) + v * 3 + d;
            const size_t bstride = (size_t)atoms * (DV * 3);
            out_atm[(size_t)(bb0 + 0) * bstride + row] = a0;
            out_atm[(size_t)(bb0 + 1) * bstride + row] = a1;
            out_atm[(size_t)(bb0 + 2) * bstride + row] = a2;
            out_atm[(size_t)(bb0 + 3) * bstride + row] = a3;
        }
    }
}

// ---------------------------------------------------------------------------
// Launch: d_out = concat(x_v_atm.ravel(), x_v_amn.ravel())
// ---------------------------------------------------------------------------
extern "C" void kernel_launch(void* const* d_in, const int* in_sizes, int n_in,
                              void* d_out, int out_size) {
    const float* pos_atm = (const float*)d_in[0];
    const float* pos_amn = (const float*)d_in[1];
    const float* W_amn   = (const float*)d_in[2];
    const float* W_atm   = (const float*)d_in[3];
    const int*   seq     = (const int*)d_in[4];

    const int n_res = in_sizes[4];                  // 2048
    const int B     = in_sizes[1] / (n_res * 3);    // 16
    const int atoms = in_sizes[0] / (B * 3);        // 15036

    float* out_atm = (float*)d_out;
    float* out_amn = out_atm + (size_t)B * atoms * DV * 3;

    scan_starts_kernel<<<1, 1024>>>(seq, n_res);
    posmix_kernel<<<n_res, TPB>>>(pos_atm, pos_amn, W_amn, W_atm, seq,
                                  out_atm, out_amn, B, n_res, atoms);
}